// round 13
// baseline (speedup 1.0000x reference)
#include <cuda_runtime.h>
#include <cuda_fp16.h>
#include <cstdint>
#include <cstddef>

// ---------------------------------------------------------------------------
// 20 independent GEMMs (block-diagonal ensemble linear)
//   x:[32768,4000] f32, W:[2000,4000] f32, out:[32768,2000] f32
//   block n: out[:,n*100:+100] = x[:,n*200:+200] @ W[n*100:+100, n*200:+200]^T
//
// R13: HYBRID split of the 100 output cols:
//   cols  0..87 : fp16 HMMA m16n8k16 (fp32 accum) — 11 n8 tiles, NO padding
//   cols 88..99 : exact fp32 scalar FFMA (fma pipe, pack-free; 1 row x 6
//                 contiguous cols per thread)
// Rationale: measured invariant ~220 MAC/cyc/SM on the legacy mma.sync path
// across all prior configs => tensor-roofline-bound. Cut tensor MACs 112->88
// cols (201us floor) and run the remaining 12 cols concurrently on the idle
// fma pipe (needs only ~46% of it). Persistent CTAs 20x7, 512 thr, W resident,
// 3-slot cp.async A ring.
// ---------------------------------------------------------------------------

static constexpr int NUM     = 20;
static constexpr int IN_SZ   = 200;
static constexpr int OUT_SZ  = 100;
static constexpr int X_LD    = 4000;
static constexpr int W_LD    = 4000;
static constexpr int OUT_LD  = 2000;

static constexpr int M_TILE  = 256;
static constexpr int KCH     = 5;                 // 4x48 + 1x8
static constexpr int MT_PER_N   = 128;            // 32768/256
static constexpr int CTAS_PER_N = 7;

static constexpr int N_TEN   = 88;                // tensor cols (11 n8 tiles)
static constexpr int N_SIMT  = 12;                // simt cols 88..99

static constexpr int NSLOT   = 3;                 // A ring depth
static constexpr int STR_A   = 52;                // A row stride (f32)
static constexpr int STR_BH  = 216;               // tensor-B row stride (halves)
static constexpr int STR_WS  = 204;               // simt-W row stride (f32)

static constexpr int A_ELEMS = M_TILE * STR_A;            // 13312 f32 / slot
static constexpr int B_BYTES = N_TEN * STR_BH * 2;        // 38016
static constexpr int WS_BYTES = N_SIMT * STR_WS * 4;      // 9792
static constexpr int OFF_WS  = B_BYTES;                   // 38016
static constexpr int OFF_A   = B_BYTES + WS_BYTES;        // 47808
static constexpr int A_BYTES = NSLOT * A_ELEMS * 4;       // 159744
static constexpr int SMEM_BYTES = OFF_A + A_BYTES;        // 207552

static constexpr int THREADS = 512;               // 16 warps: 8(wm) x 2(wn)
// tensor warp tile: 32(M) x 48/40(N): 2 m16 x (6 or 5) n8

// ---------------------------------------------------------------------------
__device__ __forceinline__ uint32_t smem_u32(const void* p) {
    uint32_t a;
    asm("{ .reg .u64 t; cvta.to.shared.u64 t, %1; cvt.u32.u64 %0, t; }"
        : "=r"(a) : "l"(p));
    return a;
}
__device__ __forceinline__ void cp16(uint32_t dst, const float* src) {
    asm volatile("cp.async.cg.shared.global [%0], [%1], 16;"
                 :: "r"(dst), "l"(src));
}
#define CP_COMMIT() asm volatile("cp.async.commit_group;" ::: "memory")
#define CP_WAIT(n)  asm volatile("cp.async.wait_group %0;" :: "n"(n) : "memory")

// pack two f32 -> f16x2 reg; lo half = first (lower-k) element
__device__ __forceinline__ uint32_t cvt_f16x2(float lo, float hi) {
    uint32_t r;
    asm("cvt.rn.f16x2.f32 %0, %1, %2;" : "=r"(r) : "f"(hi), "f"(lo));
    return r;
}

// D(16x8,f32) += A(16x16,f16) * B(16x8,f16)  [row.col]
__device__ __forceinline__ void mma_f16_k16(float c[4],
                                            uint32_t a0, uint32_t a1, uint32_t a2, uint32_t a3,
                                            uint32_t b0, uint32_t b1) {
    asm volatile(
        "mma.sync.aligned.m16n8k16.row.col.f32.f16.f16.f32 "
        "{%0,%1,%2,%3}, {%4,%5,%6,%7}, {%8,%9}, {%0,%1,%2,%3};"
        : "+f"(c[0]), "+f"(c[1]), "+f"(c[2]), "+f"(c[3])
        : "r"(a0), "r"(a1), "r"(a2), "r"(a3), "r"(b0), "r"(b1));
}
// D(16x8,f32) += A(16x8,f16) * B(8x8,f16)  [row.col]
__device__ __forceinline__ void mma_f16_k8(float c[4],
                                           uint32_t a0, uint32_t a1, uint32_t b0) {
    asm volatile(
        "mma.sync.aligned.m16n8k8.row.col.f32.f16.f16.f32 "
        "{%0,%1,%2,%3}, {%4,%5}, {%6}, {%0,%1,%2,%3};"
        : "+f"(c[0]), "+f"(c[1]), "+f"(c[2]), "+f"(c[3])
        : "r"(a0), "r"(a1), "r"(b0));
}

// ---------------------------------------------------------------------------
// One CTA = ensemble block n, M-tiles {cta_m, cta_m+7, ...} (M_TILE=256)
// ---------------------------------------------------------------------------
__global__ void __launch_bounds__(THREADS, 1)
ensemble_linear_hyb88_kernel(const float* __restrict__ x,
                             const float* __restrict__ W,
                             float* __restrict__ out) {
    extern __shared__ char smem[];
    __half* Bh  = (__half*)smem;                 // [88][216] fp16, resident
    float*  Ws  = (float*)(smem + OFF_WS);       // [12][204] f32, resident
    float*  Arn = (float*)(smem + OFF_A);        // [3][256*52] f32 ring
    const uint32_t a_base = smem_u32(Arn);

    const int tid = threadIdx.x;
    const int wid = tid >> 5;
    const int lid = tid & 31;
    const int g   = lid >> 2;    // 0..7
    const int tg  = lid & 3;     // 0..3
    const int wm  = wid >> 1;    // 0..7 (M)
    const int wn  = wid & 1;     // 0..1 (N)
    const int jmax = 6 - wn;     // 6 tensor n8-tiles for wn=0, 5 for wn=1

    // SIMT assignment: 1 row x 6 contiguous cols per thread
    const int srow = tid >> 1;          // 0..255
    const int c0   = 6 * (tid & 1);     // 0 or 6 -> cols 88..93 / 94..99

    const int n     = blockIdx.x;      // 0..19
    const int cta_m = blockIdx.y;      // 0..6
    const int n_mt  = (MT_PER_N - cta_m + CTAS_PER_N - 1) / CTAS_PER_N;
    const int total_chunks = n_mt * KCH;

    // ---- one-time W staging ------------------------------------------------
    {
        const float* wbase = W + (size_t)n * OUT_SZ * W_LD + (size_t)n * IN_SZ;
        // tensor rows 0..87 -> fp16
        for (int idx = tid; idx < N_TEN * 50; idx += THREADS) {
            int r  = idx / 50;
            int c4 = idx - r * 50;
            float4 v = *(const float4*)(wbase + (size_t)r * W_LD + c4 * 4);
            uint2 u;
            u.x = cvt_f16x2(v.x, v.y);
            u.y = cvt_f16x2(v.z, v.w);
            *(uint2*)(Bh + r * STR_BH + c4 * 4) = u;
        }
        // simt rows 88..99 -> exact f32, [c][k] layout
        for (int idx = tid; idx < N_SIMT * 50; idx += THREADS) {
            int cc = idx / 50;
            int c4 = idx - cc * 50;
            float4 v = *(const float4*)(wbase + (size_t)(N_TEN + cc) * W_LD + c4 * 4);
            *(float4*)(Ws + cc * STR_WS + c4 * 4) = v;
        }
    }

    const float* xbase = x + (size_t)n * IN_SZ;

    // ---- A chunk producer (cp.async). kc<4: 48 cols; kc==4: 8 cols ---------
    auto produce = [&](int c) {
        if (c < total_chunks) {
            int ml = c / KCH;
            int kc = c - ml * KCH;
            int mt = cta_m + ml * CTAS_PER_N;
            const float* xs = xbase + (size_t)mt * M_TILE * X_LD + kc * 48;
            uint32_t dst = a_base + (uint32_t)((c % NSLOT) * A_ELEMS) * 4u;
            if (kc < 4) {
                #pragma unroll
                for (int j = 0; j < 6; ++j) {
                    int idx = tid + j * THREADS;
                    int r = idx / 12;
                    int i = idx - r * 12;
                    cp16(dst + (uint32_t)(r * STR_A + i * 4) * 4u,
                         xs + (size_t)r * X_LD + i * 4);
                }
            } else {
                int r = tid >> 1;
                int i = tid & 1;
                cp16(dst + (uint32_t)(r * STR_A + i * 4) * 4u,
                     xs + (size_t)r * X_LD + i * 4);
            }
        }
        CP_COMMIT();
    };

    float acc[2][6][4];                 // tensor accumulators (wn=1 uses 5)
    float acc6[6];                      // simt accumulators
    #pragma unroll
    for (int t = 0; t < 2; ++t)
        #pragma unroll
        for (int j = 0; j < 6; ++j)
            #pragma unroll
            for (int q = 0; q < 4; ++q) acc[t][j][q] = 0.0f;
    #pragma unroll
    for (int j = 0; j < 6; ++j) acc6[j] = 0.0f;

    produce(0);
    produce(1);

    // ---- mainloop ----------------------------------------------------------
    for (int c = 0; c < total_chunks; ++c) {
        CP_WAIT(1);            // chunk c resident
        __syncthreads();       // visible to all; chunk c-1 fully consumed

        produce(c + 2);        // refills slot (c-1)%3 — safe after the sync

        const float* Ab = Arn + (c % NSLOT) * A_ELEMS;
        const int kc = c % KCH;
        const int kg = kc * 48;

        // ===== tensor: cols 0..87 =======================================
        if (kc < 4) {
            #pragma unroll
            for (int ks = 0; ks < 3; ++ks) {      // 3 k16 steps
                const int k0 = ks * 16;
                uint32_t a[2][4];
                #pragma unroll
                for (int t = 0; t < 2; ++t) {
                    const int row = wm * 32 + t * 16 + g;
                    const float* base = Ab + row * STR_A + k0 + 2 * tg;
                    float2 v00 = *(const float2*)(base);
                    float2 v10 = *(const float2*)(base + 8 * STR_A);
                    float2 v01 = *(const float2*)(base + 8);
                    float2 v11 = *(const float2*)(base + 8 * STR_A + 8);
                    a[t][0] = cvt_f16x2(v00.x, v00.y);
                    a[t][1] = cvt_f16x2(v10.x, v10.y);
                    a[t][2] = cvt_f16x2(v01.x, v01.y);
                    a[t][3] = cvt_f16x2(v11.x, v11.y);
                }
                uint32_t b[6][2];
                #pragma unroll
                for (int j = 0; j < 6; ++j) {
                    if (j < jmax) {
                        const int col = wn * 48 + j * 8 + g;
                        const uint32_t* bp =
                            (const uint32_t*)(Bh + col * STR_BH + kg + k0 + 2 * tg);
                        b[j][0] = bp[0];
                        b[j][1] = bp[4];
                    }
                }
                #pragma unroll
                for (int t = 0; t < 2; ++t)
                    #pragma unroll
                    for (int j = 0; j < 6; ++j)
                        if (j < jmax)
                            mma_f16_k16(acc[t][j], a[t][0], a[t][1], a[t][2], a[t][3],
                                        b[j][0], b[j][1]);
            }
        } else {
            // tail: one k8 step (k = 192..199)
            uint32_t a[2][2];
            #pragma unroll
            for (int t = 0; t < 2; ++t) {
                const int row = wm * 32 + t * 16 + g;
                const float* base = Ab + row * STR_A + 2 * tg;
                float2 v0 = *(const float2*)(base);
                float2 v1 = *(const float2*)(base + 8 * STR_A);
                a[t][0] = cvt_f16x2(v0.x, v0.y);
                a[t][1] = cvt_f16x2(v1.x, v1.y);
            }
            uint32_t b[6];
            #pragma unroll
            for (int j = 0; j < 6; ++j) {
                if (j < jmax) {
                    const int col = wn * 48 + j * 8 + g;
                    b[j] = *(const uint32_t*)(Bh + col * STR_BH + kg + 2 * tg);
                }
            }
            #pragma unroll
            for (int t = 0; t < 2; ++t)
                #pragma unroll
                for (int j = 0; j < 6; ++j)
                    if (j < jmax)
                        mma_f16_k8(acc[t][j], a[t][0], a[t][1], b[j]);
        }

        // ===== simt: cols 88..99, exact fp32 (fma pipe) =====================
        {
            const float* xr = Ab + srow * STR_A;
            const int nk4 = (kc < 4) ? 12 : 2;
            for (int k4 = 0; k4 < nk4; ++k4) {
                float4 xv = *(const float4*)(xr + 4 * k4);
                #pragma unroll
                for (int j = 0; j < 6; ++j) {
                    const float4 wv =
                        *(const float4*)(Ws + (c0 + j) * STR_WS + kg + 4 * k4);
                    acc6[j] += xv.x * wv.x;
                    acc6[j] += xv.y * wv.y;
                    acc6[j] += xv.z * wv.z;
                    acc6[j] += xv.w * wv.w;
                }
            }
        }

        // ---- per-M-tile epilogue after last k-chunk ------------------------
        if (kc == KCH - 1) {
            const int mt = cta_m + (c / KCH) * CTAS_PER_N;
            // tensor cols 0..87
            const int row_base = mt * M_TILE + wm * 32;
            #pragma unroll
            for (int t = 0; t < 2; ++t) {
                const int r0 = row_base + t * 16 + g;
                float* orow = out + (size_t)r0 * OUT_LD + (size_t)n * OUT_SZ;
                #pragma unroll
                for (int j = 0; j < 6; ++j) {
                    if (j < jmax) {
                        const int cgl = wn * 48 + j * 8 + 2 * tg;   // 0..86
                        *(float2*)(orow + cgl) =
                            make_float2(acc[t][j][0], acc[t][j][1]);
                        *(float2*)(orow + (size_t)8 * OUT_LD + cgl) =
                            make_float2(acc[t][j][2], acc[t][j][3]);
                    }
                    #pragma unroll
                    for (int q = 0; q < 4; ++q) acc[t][j][q] = 0.0f;
                }
            }
            // simt cols 88..99 (6 contiguous floats per thread)
            {
                float* op = out + (size_t)(mt * M_TILE + srow) * OUT_LD
                                + (size_t)n * OUT_SZ + N_TEN + c0;
                *(float2*)(op + 0) = make_float2(acc6[0], acc6[1]);
                *(float2*)(op + 2) = make_float2(acc6[2], acc6[3]);
                *(float2*)(op + 4) = make_float2(acc6[4], acc6[5]);
                #pragma unroll
                for (int j = 0; j < 6; ++j) acc6[j] = 0.0f;
            }
        }
    }
}

// ---------------------------------------------------------------------------
extern "C" void kernel_launch(void* const* d_in, const int* in_sizes, int n_in,
                              void* d_out, int out_size) {
    const float* x = (const float*)d_in[0];   // [32768, 4000]
    const float* W = (const float*)d_in[1];   // [2000, 4000]
    float* out = (float*)d_out;               // [32768, 2000]

    static bool attr_set = false;
    if (!attr_set) {
        cudaFuncSetAttribute(ensemble_linear_hyb88_kernel,
                             cudaFuncAttributeMaxDynamicSharedMemorySize,
                             SMEM_BYTES);
        attr_set = true;
    }

    dim3 grid(NUM, CTAS_PER_N, 1);            // 20 x 7 = 140 CTAs
    ensemble_linear_hyb88_kernel<<<grid, THREADS, SMEM_BYTES>>>(x, W, out);
}

// round 14
// speedup vs baseline: 1.4875x; 1.4875x over previous
#include <cuda_runtime.h>
#include <cuda_fp16.h>
#include <cstdint>
#include <cstddef>

// ---------------------------------------------------------------------------
// 20 independent GEMMs (block-diagonal ensemble linear)
//   x:[32768,4000] f32, W:[2000,4000] f32, out:[32768,2000] f32
//   block n: out[:,n*100:+100] = x[:,n*200:+200] @ W[n*100:+100, n*200:+200]^T
//
// R14 = R12 (best, 256us) + two bookkeeping fixes:
//   1) N padding 112 -> 104 (13 n8 tiles, 7/6 split): -7.1% tensor MACs
//   2) flattened persistent grid of 148 CTAs over 2560 (n, M-tile) units:
//      all SMs busy, max 18 units/CTA (was 19 on 140 CTAs). A CTA spans at
//      most 2 ensemble blocks; W re-staged once on the block switch.
// Core unchanged: fp16 m16n8k16 HMMA (fp32 accum), 512 threads/CTA,
// W resident in SMEM as fp16, 3-slot cp.async ring of 49KB A chunks.
// ---------------------------------------------------------------------------

static constexpr int NUM     = 20;
static constexpr int IN_SZ   = 200;
static constexpr int OUT_SZ  = 100;
static constexpr int X_LD    = 4000;
static constexpr int W_LD    = 4000;
static constexpr int OUT_LD  = 2000;

static constexpr int M_TILE  = 256;
static constexpr int KCH     = 5;                 // 4x48 + 1x8
static constexpr int MT_PER_N = 128;              // 32768/256
static constexpr int UNITS   = NUM * MT_PER_N;    // 2560 work units
static constexpr int NCTAS   = 148;               // one per SM

static constexpr int N_TILE  = 104;               // 13 n8 tiles (pad 100->104)
static constexpr int NSLOT   = 3;                 // A ring depth
static constexpr int STR_A   = 52;                // A row stride (f32)
static constexpr int STR_BH  = 216;               // B row stride (halves)

static constexpr int A_ELEMS = M_TILE * STR_A;            // 13312 f32 / slot
static constexpr int B_BYTES = N_TILE * STR_BH * 2;       // 44928
static constexpr int A_BYTES = NSLOT * A_ELEMS * 4;       // 159744
static constexpr int SMEM_BYTES = B_BYTES + A_BYTES;      // 204672

static constexpr int THREADS = 512;               // 16 warps: 8(wm) x 2(wn)
// tensor warp tile: 32(M) x 56/48(N): 2 m16 x (7 or 6) n8

// ---------------------------------------------------------------------------
__device__ __forceinline__ uint32_t smem_u32(const void* p) {
    uint32_t a;
    asm("{ .reg .u64 t; cvta.to.shared.u64 t, %1; cvt.u32.u64 %0, t; }"
        : "=r"(a) : "l"(p));
    return a;
}
__device__ __forceinline__ void cp16(uint32_t dst, const float* src) {
    asm volatile("cp.async.cg.shared.global [%0], [%1], 16;"
                 :: "r"(dst), "l"(src));
}
#define CP_COMMIT() asm volatile("cp.async.commit_group;" ::: "memory")
#define CP_WAIT(n)  asm volatile("cp.async.wait_group %0;" :: "n"(n) : "memory")

// pack two f32 -> f16x2 reg; lo half = first (lower-k) element
__device__ __forceinline__ uint32_t cvt_f16x2(float lo, float hi) {
    uint32_t r;
    asm("cvt.rn.f16x2.f32 %0, %1, %2;" : "=r"(r) : "f"(hi), "f"(lo));
    return r;
}

// D(16x8,f32) += A(16x16,f16) * B(16x8,f16)  [row.col]
__device__ __forceinline__ void mma_f16_k16(float c[4],
                                            uint32_t a0, uint32_t a1, uint32_t a2, uint32_t a3,
                                            uint32_t b0, uint32_t b1) {
    asm volatile(
        "mma.sync.aligned.m16n8k16.row.col.f32.f16.f16.f32 "
        "{%0,%1,%2,%3}, {%4,%5,%6,%7}, {%8,%9}, {%0,%1,%2,%3};"
        : "+f"(c[0]), "+f"(c[1]), "+f"(c[2]), "+f"(c[3])
        : "r"(a0), "r"(a1), "r"(a2), "r"(a3), "r"(b0), "r"(b1));
}
// D(16x8,f32) += A(16x8,f16) * B(8x8,f16)  [row.col]
__device__ __forceinline__ void mma_f16_k8(float c[4],
                                           uint32_t a0, uint32_t a1, uint32_t b0) {
    asm volatile(
        "mma.sync.aligned.m16n8k8.row.col.f32.f16.f16.f32 "
        "{%0,%1,%2,%3}, {%4,%5}, {%6}, {%0,%1,%2,%3};"
        : "+f"(c[0]), "+f"(c[1]), "+f"(c[2]), "+f"(c[3])
        : "r"(a0), "r"(a1), "r"(b0));
}

// ---------------------------------------------------------------------------
// Persistent CTA over flattened (n, M-tile) units u = n*128 + mt.
// ---------------------------------------------------------------------------
__global__ void __launch_bounds__(THREADS, 1)
ensemble_linear_f16u_kernel(const float* __restrict__ x,
                            const float* __restrict__ W,
                            float* __restrict__ out) {
    extern __shared__ char smem[];
    __half* Bh  = (__half*)smem;                 // [104][216] fp16
    float*  Arn = (float*)(smem + B_BYTES);      // [3][256*52] f32 ring
    const uint32_t a_base = smem_u32(Arn);

    const int tid = threadIdx.x;
    const int wid = tid >> 5;
    const int lid = tid & 31;
    const int g   = lid >> 2;    // 0..7
    const int tg  = lid & 3;     // 0..3
    const int wm  = wid >> 1;    // 0..7 (M)
    const int wn  = wid & 1;     // 0..1 (N)
    const int jmax = 7 - wn;     // 7 n8 tiles for wn=0 (cols 0..55), 6 for wn=1 (56..103)

    const int cta    = blockIdx.x;
    const int ustart = (cta * UNITS) / NCTAS;
    const int uend   = ((cta + 1) * UNITS) / NCTAS;
    const int total_chunks = (uend - ustart) * KCH;

    // ---- W staging (rows 0..99 -> fp16, rows 100..103 zero) ----------------
    auto stage_W = [&](int nn) {
        const float* wbase = W + (size_t)nn * OUT_SZ * W_LD + (size_t)nn * IN_SZ;
        for (int idx = tid; idx < OUT_SZ * 50; idx += THREADS) {
            int r  = idx / 50;
            int c4 = idx - r * 50;
            float4 v = *(const float4*)(wbase + (size_t)r * W_LD + c4 * 4);
            uint2 u;
            u.x = cvt_f16x2(v.x, v.y);
            u.y = cvt_f16x2(v.z, v.w);
            *(uint2*)(Bh + r * STR_BH + c4 * 4) = u;
        }
        for (int i = tid; i < 4 * STR_BH; i += THREADS) {
            int r = 100 + i / STR_BH;
            int cc = i - (i / STR_BH) * STR_BH;
            Bh[r * STR_BH + cc] = __float2half(0.0f);
        }
    };

    // ---- A chunk producer (cp.async). kc<4: 48 cols; kc==4: 8 cols ---------
    auto produce = [&](int c) {
        if (c < total_chunks) {
            const int u  = ustart + c / KCH;
            const int kc = c % KCH;
            const int np = u >> 7;       // u / 128
            const int mt = u & 127;
            const float* xs = x + (size_t)np * IN_SZ
                                + (size_t)mt * M_TILE * X_LD + kc * 48;
            uint32_t dst = a_base + (uint32_t)((c % NSLOT) * A_ELEMS) * 4u;
            if (kc < 4) {
                #pragma unroll
                for (int j = 0; j < 6; ++j) {
                    int idx = tid + j * THREADS;
                    int r = idx / 12;
                    int i = idx - r * 12;
                    cp16(dst + (uint32_t)(r * STR_A + i * 4) * 4u,
                         xs + (size_t)r * X_LD + i * 4);
                }
            } else {
                int r = tid >> 1;
                int i = tid & 1;
                cp16(dst + (uint32_t)(r * STR_A + i * 4) * 4u,
                     xs + (size_t)r * X_LD + i * 4);
            }
        }
        CP_COMMIT();
    };

    float acc[2][7][4];
    #pragma unroll
    for (int t = 0; t < 2; ++t)
        #pragma unroll
        for (int j = 0; j < 7; ++j)
            #pragma unroll
            for (int q = 0; q < 4; ++q) acc[t][j][q] = 0.0f;

    int cur_n = ustart >> 7;
    stage_W(cur_n);                 // visibility: first loop-top __syncthreads

    produce(0);
    produce(1);

    // ---- mainloop ----------------------------------------------------------
    for (int c = 0; c < total_chunks; ++c) {
        CP_WAIT(1);            // chunk c resident
        __syncthreads();       // chunk c (and any W staging) visible; c-1 consumed

        const int u  = ustart + c / KCH;
        const int kc = c % KCH;
        const int n  = u >> 7;
        const int mt = u & 127;

        if (n != cur_n) {      // block switch (<=1 per CTA); only at kc==0
            stage_W(n);
            cur_n = n;
            __syncthreads();
        }

        produce(c + 2);        // refills slot (c-1)%3 — safe after the sync

        const float* Ab = Arn + (c % NSLOT) * A_ELEMS;
        const int kg = kc * 48;

        if (kc < 4) {
            #pragma unroll
            for (int ks = 0; ks < 3; ++ks) {      // 3 k16 steps
                const int k0 = ks * 16;
                uint32_t a[2][4];
                #pragma unroll
                for (int t = 0; t < 2; ++t) {
                    const int row = wm * 32 + t * 16 + g;
                    const float* base = Ab + row * STR_A + k0 + 2 * tg;
                    float2 v00 = *(const float2*)(base);
                    float2 v10 = *(const float2*)(base + 8 * STR_A);
                    float2 v01 = *(const float2*)(base + 8);
                    float2 v11 = *(const float2*)(base + 8 * STR_A + 8);
                    a[t][0] = cvt_f16x2(v00.x, v00.y);
                    a[t][1] = cvt_f16x2(v10.x, v10.y);
                    a[t][2] = cvt_f16x2(v01.x, v01.y);
                    a[t][3] = cvt_f16x2(v11.x, v11.y);
                }
                uint32_t b[7][2];
                #pragma unroll
                for (int j = 0; j < 7; ++j) {
                    if (j < jmax) {
                        const int col = wn * 56 + j * 8 + g;
                        const uint32_t* bp =
                            (const uint32_t*)(Bh + col * STR_BH + kg + k0 + 2 * tg);
                        b[j][0] = bp[0];
                        b[j][1] = bp[4];   // +8 halves = +16B
                    }
                }
                #pragma unroll
                for (int t = 0; t < 2; ++t)
                    #pragma unroll
                    for (int j = 0; j < 7; ++j)
                        if (j < jmax)
                            mma_f16_k16(acc[t][j], a[t][0], a[t][1], a[t][2], a[t][3],
                                        b[j][0], b[j][1]);
            }
        } else {
            // tail: one k8 step (k = 192..199)
            uint32_t a[2][2];
            #pragma unroll
            for (int t = 0; t < 2; ++t) {
                const int row = wm * 32 + t * 16 + g;
                const float* base = Ab + row * STR_A + 2 * tg;
                float2 v0 = *(const float2*)(base);
                float2 v1 = *(const float2*)(base + 8 * STR_A);
                a[t][0] = cvt_f16x2(v0.x, v0.y);
                a[t][1] = cvt_f16x2(v1.x, v1.y);
            }
            uint32_t b[7];
            #pragma unroll
            for (int j = 0; j < 7; ++j) {
                if (j < jmax) {
                    const int col = wn * 56 + j * 8 + g;
                    b[j] = *(const uint32_t*)(Bh + col * STR_BH + kg + 2 * tg);
                }
            }
            #pragma unroll
            for (int t = 0; t < 2; ++t)
                #pragma unroll
                for (int j = 0; j < 7; ++j)
                    if (j < jmax)
                        mma_f16_k8(acc[t][j], a[t][0], a[t][1], b[j]);
        }

        // ---- per-M-tile epilogue after last k-chunk ------------------------
        if (kc == KCH - 1) {
            const int row_base = mt * M_TILE + wm * 32;
            #pragma unroll
            for (int t = 0; t < 2; ++t) {
                const int r0 = row_base + t * 16 + g;
                float* orow = out + (size_t)r0 * OUT_LD + (size_t)n * OUT_SZ;
                #pragma unroll
                for (int j = 0; j < 7; ++j) {
                    if (j < jmax) {
                        const int cgl = wn * 56 + j * 8 + 2 * tg;   // even, 0..102
                        if (cgl < OUT_SZ) {
                            *(float2*)(orow + cgl) =
                                make_float2(acc[t][j][0], acc[t][j][1]);
                            *(float2*)(orow + (size_t)8 * OUT_LD + cgl) =
                                make_float2(acc[t][j][2], acc[t][j][3]);
                        }
                    }
                    #pragma unroll
                    for (int q = 0; q < 4; ++q) acc[t][j][q] = 0.0f;
                }
            }
        }
    }
}

// ---------------------------------------------------------------------------
extern "C" void kernel_launch(void* const* d_in, const int* in_sizes, int n_in,
                              void* d_out, int out_size) {
    const float* x = (const float*)d_in[0];   // [32768, 4000]
    const float* W = (const float*)d_in[1];   // [2000, 4000]
    float* out = (float*)d_out;               // [32768, 2000]

    static bool attr_set = false;
    if (!attr_set) {
        cudaFuncSetAttribute(ensemble_linear_f16u_kernel,
                             cudaFuncAttributeMaxDynamicSharedMemorySize,
                             SMEM_BYTES);
        attr_set = true;
    }

    ensemble_linear_f16u_kernel<<<NCTAS, THREADS, SMEM_BYTES>>>(x, W, out);
}

// round 15
// speedup vs baseline: 1.6406x; 1.1029x over previous
#include <cuda_runtime.h>
#include <cuda_fp16.h>
#include <cstdint>
#include <cstddef>

// ---------------------------------------------------------------------------
// 20 independent GEMMs (block-diagonal ensemble linear)
//   x:[32768,4000] f32, W:[2000,4000] f32, out:[32768,2000] f32
//   block n: out[:,n*100:+100] = x[:,n*200:+200] @ W[n*100:+100, n*200:+200]^T
//
// R15 = R12 core + A-fragment bank-conflict fix + 148-CTA flattened grid.
//   * STR_A 52 -> 56: A-frag LDS.64 banks (24g+2tg) mod 32 -> all 16 lanes
//     per phase distinct (52 gave 2-way conflicts on both phases).
//   * N_TILE back to 112 (7/7 balanced warp columns; the R14 104/7-6 split
//     didn't shorten the barrier critical path).
//   * persistent flattened grid of 148 CTAs over 2560 (n, M-tile) units.
// Core: fp16 m16n8k16 HMMA (fp32 accum), 512 thr, W resident fp16 in SMEM,
// 3-slot cp.async ring of 256x48-f32 A chunks (KCH = 4x48 + 1x8).
// ---------------------------------------------------------------------------

static constexpr int NUM     = 20;
static constexpr int IN_SZ   = 200;
static constexpr int OUT_SZ  = 100;
static constexpr int X_LD    = 4000;
static constexpr int W_LD    = 4000;
static constexpr int OUT_LD  = 2000;

static constexpr int M_TILE  = 256;
static constexpr int KCH     = 5;                 // 4x48 + 1x8
static constexpr int MT_PER_N = 128;              // 32768/256
static constexpr int UNITS   = NUM * MT_PER_N;    // 2560 work units
static constexpr int NCTAS   = 148;               // one per SM

static constexpr int N_TILE  = 112;               // 14 n8 tiles, 7/7 balanced
static constexpr int NSLOT   = 3;                 // A ring depth
static constexpr int STR_A   = 56;                // conflict-free A row stride (f32)
static constexpr int STR_BH  = 216;               // B row stride (halves)

static constexpr int A_ELEMS = M_TILE * STR_A;            // 14336 f32 / slot
static constexpr int B_BYTES = N_TILE * STR_BH * 2;       // 48384
static constexpr int A_BYTES = NSLOT * A_ELEMS * 4;       // 172032
static constexpr int SMEM_BYTES = B_BYTES + A_BYTES;      // 220416

static constexpr int THREADS = 512;               // 16 warps: 8(wm) x 2(wn)
// warp tile 32(M) x 56(N): 2 m16 x 7 n8

// ---------------------------------------------------------------------------
__device__ __forceinline__ uint32_t smem_u32(const void* p) {
    uint32_t a;
    asm("{ .reg .u64 t; cvta.to.shared.u64 t, %1; cvt.u32.u64 %0, t; }"
        : "=r"(a) : "l"(p));
    return a;
}
__device__ __forceinline__ void cp16(uint32_t dst, const float* src) {
    asm volatile("cp.async.cg.shared.global [%0], [%1], 16;"
                 :: "r"(dst), "l"(src));
}
#define CP_COMMIT() asm volatile("cp.async.commit_group;" ::: "memory")
#define CP_WAIT(n)  asm volatile("cp.async.wait_group %0;" :: "n"(n) : "memory")

// pack two f32 -> f16x2 reg; lo half = first (lower-k) element
__device__ __forceinline__ uint32_t cvt_f16x2(float lo, float hi) {
    uint32_t r;
    asm("cvt.rn.f16x2.f32 %0, %1, %2;" : "=r"(r) : "f"(hi), "f"(lo));
    return r;
}

// D(16x8,f32) += A(16x16,f16) * B(16x8,f16)  [row.col]
__device__ __forceinline__ void mma_f16_k16(float c[4],
                                            uint32_t a0, uint32_t a1, uint32_t a2, uint32_t a3,
                                            uint32_t b0, uint32_t b1) {
    asm volatile(
        "mma.sync.aligned.m16n8k16.row.col.f32.f16.f16.f32 "
        "{%0,%1,%2,%3}, {%4,%5,%6,%7}, {%8,%9}, {%0,%1,%2,%3};"
        : "+f"(c[0]), "+f"(c[1]), "+f"(c[2]), "+f"(c[3])
        : "r"(a0), "r"(a1), "r"(a2), "r"(a3), "r"(b0), "r"(b1));
}
// D(16x8,f32) += A(16x8,f16) * B(8x8,f16)  [row.col]
__device__ __forceinline__ void mma_f16_k8(float c[4],
                                           uint32_t a0, uint32_t a1, uint32_t b0) {
    asm volatile(
        "mma.sync.aligned.m16n8k8.row.col.f32.f16.f16.f32 "
        "{%0,%1,%2,%3}, {%4,%5}, {%6}, {%0,%1,%2,%3};"
        : "+f"(c[0]), "+f"(c[1]), "+f"(c[2]), "+f"(c[3])
        : "r"(a0), "r"(a1), "r"(b0));
}

// ---------------------------------------------------------------------------
// Persistent CTA over flattened (n, M-tile) units u = n*128 + mt.
// ---------------------------------------------------------------------------
__global__ void __launch_bounds__(THREADS, 1)
ensemble_linear_f16s_kernel(const float* __restrict__ x,
                            const float* __restrict__ W,
                            float* __restrict__ out) {
    extern __shared__ char smem[];
    __half* Bh  = (__half*)smem;                 // [112][216] fp16
    float*  Arn = (float*)(smem + B_BYTES);      // [3][256*56] f32 ring
    const uint32_t a_base = smem_u32(Arn);

    const int tid = threadIdx.x;
    const int wid = tid >> 5;
    const int lid = tid & 31;
    const int g   = lid >> 2;    // 0..7
    const int tg  = lid & 3;     // 0..3
    const int wm  = wid >> 1;    // 0..7 (M)
    const int wn  = wid & 1;     // 0..1 (N)

    const int cta    = blockIdx.x;
    const int ustart = (cta * UNITS) / NCTAS;
    const int uend   = ((cta + 1) * UNITS) / NCTAS;
    const int total_chunks = (uend - ustart) * KCH;

    // ---- W staging (rows 0..99 -> fp16, rows 100..111 zero) ----------------
    auto stage_W = [&](int nn) {
        const float* wbase = W + (size_t)nn * OUT_SZ * W_LD + (size_t)nn * IN_SZ;
        for (int idx = tid; idx < OUT_SZ * 50; idx += THREADS) {
            int r  = idx / 50;
            int c4 = idx - r * 50;
            float4 v = *(const float4*)(wbase + (size_t)r * W_LD + c4 * 4);
            uint2 u;
            u.x = cvt_f16x2(v.x, v.y);
            u.y = cvt_f16x2(v.z, v.w);
            *(uint2*)(Bh + r * STR_BH + c4 * 4) = u;
        }
        for (int i = tid; i < 12 * STR_BH; i += THREADS) {
            int r = 100 + i / STR_BH;
            int cc = i - (i / STR_BH) * STR_BH;
            Bh[r * STR_BH + cc] = __float2half(0.0f);
        }
    };

    // ---- A chunk producer (cp.async). kc<4: 48 cols; kc==4: 8 cols ---------
    auto produce = [&](int c) {
        if (c < total_chunks) {
            const int u  = ustart + c / KCH;
            const int kc = c % KCH;
            const int np = u >> 7;       // u / 128
            const int mt = u & 127;
            const float* xs = x + (size_t)np * IN_SZ
                                + (size_t)mt * M_TILE * X_LD + kc * 48;
            uint32_t dst = a_base + (uint32_t)((c % NSLOT) * A_ELEMS) * 4u;
            if (kc < 4) {
                #pragma unroll
                for (int j = 0; j < 6; ++j) {
                    int idx = tid + j * THREADS;
                    int r = idx / 12;
                    int i = idx - r * 12;
                    cp16(dst + (uint32_t)(r * STR_A + i * 4) * 4u,
                         xs + (size_t)r * X_LD + i * 4);
                }
            } else {
                int r = tid >> 1;
                int i = tid & 1;
                cp16(dst + (uint32_t)(r * STR_A + i * 4) * 4u,
                     xs + (size_t)r * X_LD + i * 4);
            }
        }
        CP_COMMIT();
    };

    float acc[2][7][4];
    #pragma unroll
    for (int t = 0; t < 2; ++t)
        #pragma unroll
        for (int j = 0; j < 7; ++j)
            #pragma unroll
            for (int q = 0; q < 4; ++q) acc[t][j][q] = 0.0f;

    int cur_n = ustart >> 7;
    stage_W(cur_n);                 // visibility: first loop-top __syncthreads

    produce(0);
    produce(1);

    // ---- mainloop ----------------------------------------------------------
    for (int c = 0; c < total_chunks; ++c) {
        CP_WAIT(1);            // chunk c resident
        __syncthreads();       // chunk c (and any W staging) visible; c-1 consumed

        const int u  = ustart + c / KCH;
        const int kc = c % KCH;
        const int n  = u >> 7;
        const int mt = u & 127;

        if (n != cur_n) {      // block switch (<=1 per CTA); only at kc==0
            stage_W(n);
            cur_n = n;
            __syncthreads();
        }

        produce(c + 2);        // refills slot (c-1)%3 — safe after the sync

        const float* Ab = Arn + (c % NSLOT) * A_ELEMS;
        const int kg = kc * 48;

        if (kc < 4) {
            #pragma unroll
            for (int ks = 0; ks < 3; ++ks) {      // 3 k16 steps
                const int k0 = ks * 16;
                uint32_t a[2][4];
                #pragma unroll
                for (int t = 0; t < 2; ++t) {
                    const int row = wm * 32 + t * 16 + g;
                    const float* base = Ab + row * STR_A + k0 + 2 * tg;
                    float2 v00 = *(const float2*)(base);
                    float2 v10 = *(const float2*)(base + 8 * STR_A);
                    float2 v01 = *(const float2*)(base + 8);
                    float2 v11 = *(const float2*)(base + 8 * STR_A + 8);
                    a[t][0] = cvt_f16x2(v00.x, v00.y);
                    a[t][1] = cvt_f16x2(v10.x, v10.y);
                    a[t][2] = cvt_f16x2(v01.x, v01.y);
                    a[t][3] = cvt_f16x2(v11.x, v11.y);
                }
                uint32_t b[7][2];
                #pragma unroll
                for (int j = 0; j < 7; ++j) {
                    const int col = wn * 56 + j * 8 + g;
                    const uint32_t* bp =
                        (const uint32_t*)(Bh + col * STR_BH + kg + k0 + 2 * tg);
                    b[j][0] = bp[0];
                    b[j][1] = bp[4];   // +8 halves = +16B
                }
                #pragma unroll
                for (int t = 0; t < 2; ++t)
                    #pragma unroll
                    for (int j = 0; j < 7; ++j)
                        mma_f16_k16(acc[t][j], a[t][0], a[t][1], a[t][2], a[t][3],
                                    b[j][0], b[j][1]);
            }
        } else {
            // tail: one k8 step (k = 192..199)
            uint32_t a[2][2];
            #pragma unroll
            for (int t = 0; t < 2; ++t) {
                const int row = wm * 32 + t * 16 + g;
                const float* base = Ab + row * STR_A + 2 * tg;
                float2 v0 = *(const float2*)(base);
                float2 v1 = *(const float2*)(base + 8 * STR_A);
                a[t][0] = cvt_f16x2(v0.x, v0.y);
                a[t][1] = cvt_f16x2(v1.x, v1.y);
            }
            uint32_t b[7];
            #pragma unroll
            for (int j = 0; j < 7; ++j) {
                const int col = wn * 56 + j * 8 + g;
                b[j] = *(const uint32_t*)(Bh + col * STR_BH + kg + 2 * tg);
            }
            #pragma unroll
            for (int t = 0; t < 2; ++t)
                #pragma unroll
                for (int j = 0; j < 7; ++j)
                    mma_f16_k8(acc[t][j], a[t][0], a[t][1], b[j]);
        }

        // ---- per-M-tile epilogue after last k-chunk ------------------------
        if (kc == KCH - 1) {
            const int row_base = mt * M_TILE + wm * 32;
            #pragma unroll
            for (int t = 0; t < 2; ++t) {
                const int r0 = row_base + t * 16 + g;
                float* orow = out + (size_t)r0 * OUT_LD + (size_t)n * OUT_SZ;
                #pragma unroll
                for (int j = 0; j < 7; ++j) {
                    const int cgl = wn * 56 + j * 8 + 2 * tg;   // even, 0..110
                    if (cgl < OUT_SZ) {
                        *(float2*)(orow + cgl) =
                            make_float2(acc[t][j][0], acc[t][j][1]);
                        *(float2*)(orow + (size_t)8 * OUT_LD + cgl) =
                            make_float2(acc[t][j][2], acc[t][j][3]);
                    }
                    #pragma unroll
                    for (int q = 0; q < 4; ++q) acc[t][j][q] = 0.0f;
                }
            }
        }
    }
}

// ---------------------------------------------------------------------------
extern "C" void kernel_launch(void* const* d_in, const int* in_sizes, int n_in,
                              void* d_out, int out_size) {
    const float* x = (const float*)d_in[0];   // [32768, 4000]
    const float* W = (const float*)d_in[1];   // [2000, 4000]
    float* out = (float*)d_out;               // [32768, 2000]

    static bool attr_set = false;
    if (!attr_set) {
        cudaFuncSetAttribute(ensemble_linear_f16s_kernel,
                             cudaFuncAttributeMaxDynamicSharedMemorySize,
                             SMEM_BYTES);
        attr_set = true;
    }

    ensemble_linear_f16s_kernel<<<NCTAS, THREADS, SMEM_BYTES>>>(x, W, out);
}

// round 16
// speedup vs baseline: 1.7285x; 1.0536x over previous
#include <cuda_runtime.h>
#include <cuda_fp16.h>
#include <cstdint>
#include <cstddef>

// ---------------------------------------------------------------------------
// 20 independent GEMMs (block-diagonal ensemble linear)
//   x:[32768,4000] f32, W:[2000,4000] f32, out:[32768,2000] f32
//   block n: out[:,n*100:+100] = x[:,n*200:+200] @ W[n*100:+100, n*200:+200]^T
//
// R16 = R15 (239.7us) + two mainloop cuts:
//   1) K split 5 chunks -> 4 (48,48,48,56): the old 8-wide tail chunk paid a
//      full wait+sync+produce round for 4% of the work. Chunk 3 = 3xk16 + k8.
//   2) B fragments via ldmatrix.m8n8.x2 (B already fp16 in smem): 7 ldmatrix
//      replace 14 LDS.32 per k16 step. Row stride 432B -> 8 rows hit banks
//      {0,12,24,4,16,28,8,20}*4B..+3 = all 32 banks once: conflict-free.
// Core unchanged: fp16 m16n8k16 HMMA (fp32 accum), 512 thr, 148 persistent
// CTAs over 2560 units, W resident fp16, 3-slot cp.async A ring, STR_A=56
// (conflict-free two-phase LDS.64).
// ---------------------------------------------------------------------------

static constexpr int NUM     = 20;
static constexpr int IN_SZ   = 200;
static constexpr int OUT_SZ  = 100;
static constexpr int X_LD    = 4000;
static constexpr int W_LD    = 4000;
static constexpr int OUT_LD  = 2000;

static constexpr int M_TILE  = 256;
static constexpr int KCH     = 4;                 // 48,48,48,56
static constexpr int MT_PER_N = 128;              // 32768/256
static constexpr int UNITS   = NUM * MT_PER_N;    // 2560 work units
static constexpr int NCTAS   = 148;               // one per SM

static constexpr int N_TILE  = 112;               // 14 n8 tiles, 7/7 balanced
static constexpr int NSLOT   = 3;                 // A ring depth
static constexpr int STR_A   = 56;                // conflict-free A row stride (f32)
static constexpr int STR_BH  = 216;               // B row stride (halves)

static constexpr int A_ELEMS = M_TILE * STR_A;            // 14336 f32 / slot
static constexpr int B_BYTES = N_TILE * STR_BH * 2;       // 48384
static constexpr int A_BYTES = NSLOT * A_ELEMS * 4;       // 172032
static constexpr int SMEM_BYTES = B_BYTES + A_BYTES;      // 220416

static constexpr int THREADS = 512;               // 16 warps: 8(wm) x 2(wn)
// warp tile 32(M) x 56(N): 2 m16 x 7 n8

// ---------------------------------------------------------------------------
__device__ __forceinline__ uint32_t smem_u32(const void* p) {
    uint32_t a;
    asm("{ .reg .u64 t; cvta.to.shared.u64 t, %1; cvt.u32.u64 %0, t; }"
        : "=r"(a) : "l"(p));
    return a;
}
__device__ __forceinline__ void cp16(uint32_t dst, const float* src) {
    asm volatile("cp.async.cg.shared.global [%0], [%1], 16;"
                 :: "r"(dst), "l"(src));
}
#define CP_COMMIT() asm volatile("cp.async.commit_group;" ::: "memory")
#define CP_WAIT(n)  asm volatile("cp.async.wait_group %0;" :: "n"(n) : "memory")

// pack two f32 -> f16x2 reg; lo half = first (lower-k) element
__device__ __forceinline__ uint32_t cvt_f16x2(float lo, float hi) {
    uint32_t r;
    asm("cvt.rn.f16x2.f32 %0, %1, %2;" : "=r"(r) : "f"(hi), "f"(lo));
    return r;
}

// ldmatrix: two 8x8 b16 matrices; lanes 0-7 address matrix 0 rows,
// lanes 8-15 matrix 1 rows.
__device__ __forceinline__ void ldsm_x2(uint32_t& r0, uint32_t& r1, uint32_t addr) {
    asm volatile("ldmatrix.sync.aligned.m8n8.x2.shared.b16 {%0,%1}, [%2];"
                 : "=r"(r0), "=r"(r1) : "r"(addr));
}

// D(16x8,f32) += A(16x16,f16) * B(16x8,f16)  [row.col]
__device__ __forceinline__ void mma_f16_k16(float c[4],
                                            uint32_t a0, uint32_t a1, uint32_t a2, uint32_t a3,
                                            uint32_t b0, uint32_t b1) {
    asm volatile(
        "mma.sync.aligned.m16n8k16.row.col.f32.f16.f16.f32 "
        "{%0,%1,%2,%3}, {%4,%5,%6,%7}, {%8,%9}, {%0,%1,%2,%3};"
        : "+f"(c[0]), "+f"(c[1]), "+f"(c[2]), "+f"(c[3])
        : "r"(a0), "r"(a1), "r"(a2), "r"(a3), "r"(b0), "r"(b1));
}
// D(16x8,f32) += A(16x8,f16) * B(8x8,f16)  [row.col]
__device__ __forceinline__ void mma_f16_k8(float c[4],
                                           uint32_t a0, uint32_t a1, uint32_t b0) {
    asm volatile(
        "mma.sync.aligned.m16n8k8.row.col.f32.f16.f16.f32 "
        "{%0,%1,%2,%3}, {%4,%5}, {%6}, {%0,%1,%2,%3};"
        : "+f"(c[0]), "+f"(c[1]), "+f"(c[2]), "+f"(c[3])
        : "r"(a0), "r"(a1), "r"(b0));
}

// ---------------------------------------------------------------------------
// Persistent CTA over flattened (n, M-tile) units u = n*128 + mt.
// ---------------------------------------------------------------------------
__global__ void __launch_bounds__(THREADS, 1)
ensemble_linear_f16m_kernel(const float* __restrict__ x,
                            const float* __restrict__ W,
                            float* __restrict__ out) {
    extern __shared__ char smem[];
    __half* Bh  = (__half*)smem;                 // [112][216] fp16
    float*  Arn = (float*)(smem + B_BYTES);      // [3][256*56] f32 ring
    const uint32_t a_base = smem_u32(Arn);
    const uint32_t b_base = smem_u32(Bh);

    const int tid = threadIdx.x;
    const int wid = tid >> 5;
    const int lid = tid & 31;
    const int g   = lid >> 2;    // 0..7
    const int tg  = lid & 3;     // 0..3
    const int wm  = wid >> 1;    // 0..7 (M)
    const int wn  = wid & 1;     // 0..1 (N)

    // ldmatrix per-lane row address component (constant over mainloop):
    // row = wn*56 + (lid & 7), matrix-half k offset = ((lid >> 3) & 1) * 8 halves
    const uint32_t b_lane_off =
        (uint32_t)(((wn * 56 + (lid & 7)) * STR_BH + ((lid >> 3) & 1) * 8) * 2);

    const int cta    = blockIdx.x;
    const int ustart = (cta * UNITS) / NCTAS;
    const int uend   = ((cta + 1) * UNITS) / NCTAS;
    const int total_chunks = (uend - ustart) * KCH;

    // ---- W staging (rows 0..99 -> fp16, rows 100..111 zero) ----------------
    auto stage_W = [&](int nn) {
        const float* wbase = W + (size_t)nn * OUT_SZ * W_LD + (size_t)nn * IN_SZ;
        for (int idx = tid; idx < OUT_SZ * 50; idx += THREADS) {
            int r  = idx / 50;
            int c4 = idx - r * 50;
            float4 v = *(const float4*)(wbase + (size_t)r * W_LD + c4 * 4);
            uint2 u;
            u.x = cvt_f16x2(v.x, v.y);
            u.y = cvt_f16x2(v.z, v.w);
            *(uint2*)(Bh + r * STR_BH + c4 * 4) = u;
        }
        for (int i = tid; i < 12 * STR_BH; i += THREADS) {
            int r = 100 + i / STR_BH;
            int cc = i - (i / STR_BH) * STR_BH;
            Bh[r * STR_BH + cc] = __float2half(0.0f);
        }
    };

    // ---- A chunk producer (cp.async). kc<3: 48 cols; kc==3: 56 cols --------
    auto produce = [&](int c) {
        if (c < total_chunks) {
            const int u  = ustart + (c >> 2);
            const int kc = c & 3;
            const int np = u >> 7;       // u / 128
            const int mt = u & 127;
            const float* xs = x + (size_t)np * IN_SZ
                                + (size_t)mt * M_TILE * X_LD + kc * 48;
            uint32_t dst = a_base + (uint32_t)((c % NSLOT) * A_ELEMS) * 4u;
            if (kc < 3) {
                // 256 rows x 12 float4 = 3072 ops -> 6/thread
                #pragma unroll
                for (int j = 0; j < 6; ++j) {
                    int idx = tid + j * THREADS;
                    int r = idx / 12;
                    int i = idx - r * 12;
                    cp16(dst + (uint32_t)(r * STR_A + i * 4) * 4u,
                         xs + (size_t)r * X_LD + i * 4);
                }
            } else {
                // 256 rows x 14 float4 = 3584 ops -> 7/thread
                #pragma unroll
                for (int j = 0; j < 7; ++j) {
                    int idx = tid + j * THREADS;
                    int r = idx / 14;
                    int i = idx - r * 14;
                    cp16(dst + (uint32_t)(r * STR_A + i * 4) * 4u,
                         xs + (size_t)r * X_LD + i * 4);
                }
            }
        }
        CP_COMMIT();
    };

    float acc[2][7][4];
    #pragma unroll
    for (int t = 0; t < 2; ++t)
        #pragma unroll
        for (int j = 0; j < 7; ++j)
            #pragma unroll
            for (int q = 0; q < 4; ++q) acc[t][j][q] = 0.0f;

    int cur_n = ustart >> 7;
    stage_W(cur_n);                 // visibility: first loop-top __syncthreads

    produce(0);
    produce(1);

    // ---- mainloop ----------------------------------------------------------
    for (int c = 0; c < total_chunks; ++c) {
        CP_WAIT(1);            // chunk c resident
        __syncthreads();       // chunk c (and any W staging) visible; c-1 consumed

        const int u  = ustart + (c >> 2);
        const int kc = c & 3;
        const int n  = u >> 7;
        const int mt = u & 127;

        if (n != cur_n) {      // block switch (<=1 per CTA); only at kc==0
            stage_W(n);
            cur_n = n;
            __syncthreads();
        }

        produce(c + 2);        // refills slot (c-1)%3 — safe after the sync

        const float* Ab = Arn + (c % NSLOT) * A_ELEMS;
        const int kg = kc * 48;
        const uint32_t b_chunk = b_base + b_lane_off + (uint32_t)(kg * 2);

        #pragma unroll
        for (int ks = 0; ks < 3; ++ks) {      // 3 k16 steps (all chunks)
            const int k0 = ks * 16;
            uint32_t a[2][4];
            #pragma unroll
            for (int t = 0; t < 2; ++t) {
                const int row = wm * 32 + t * 16 + g;
                const float* base = Ab + row * STR_A + k0 + 2 * tg;
                float2 v00 = *(const float2*)(base);
                float2 v10 = *(const float2*)(base + 8 * STR_A);
                float2 v01 = *(const float2*)(base + 8);
                float2 v11 = *(const float2*)(base + 8 * STR_A + 8);
                a[t][0] = cvt_f16x2(v00.x, v00.y);
                a[t][1] = cvt_f16x2(v10.x, v10.y);
                a[t][2] = cvt_f16x2(v01.x, v01.y);
                a[t][3] = cvt_f16x2(v11.x, v11.y);
            }
            uint32_t b[7][2];
            #pragma unroll
            for (int j = 0; j < 7; ++j)
                ldsm_x2(b[j][0], b[j][1],
                        b_chunk + (uint32_t)((j * 8 * STR_BH + k0) * 2));
            #pragma unroll
            for (int t = 0; t < 2; ++t)
                #pragma unroll
                for (int j = 0; j < 7; ++j)
                    mma_f16_k16(acc[t][j], a[t][0], a[t][1], a[t][2], a[t][3],
                                b[j][0], b[j][1]);
        }

        if (kc == 3) {
            // extra k8 step: k = 192..199 (chunk-local cols 48..55)
            uint32_t a[2][2];
            #pragma unroll
            for (int t = 0; t < 2; ++t) {
                const int row = wm * 32 + t * 16 + g;
                const float* base = Ab + row * STR_A + 48 + 2 * tg;
                float2 v0 = *(const float2*)(base);
                float2 v1 = *(const float2*)(base + 8 * STR_A);
                a[t][0] = cvt_f16x2(v0.x, v0.y);
                a[t][1] = cvt_f16x2(v1.x, v1.y);
            }
            uint32_t b[7];
            #pragma unroll
            for (int j = 0; j < 7; ++j) {
                const int col = wn * 56 + j * 8 + g;
                b[j] = *(const uint32_t*)(Bh + col * STR_BH + 192 + 2 * tg);
            }
            #pragma unroll
            for (int t = 0; t < 2; ++t)
                #pragma unroll
                for (int j = 0; j < 7; ++j)
                    mma_f16_k8(acc[t][j], a[t][0], a[t][1], b[j]);
        }

        // ---- per-M-tile epilogue after last k-chunk ------------------------
        if (kc == KCH - 1) {
            const int row_base = mt * M_TILE + wm * 32;
            #pragma unroll
            for (int t = 0; t < 2; ++t) {
                const int r0 = row_base + t * 16 + g;
                float* orow = out + (size_t)r0 * OUT_LD + (size_t)n * OUT_SZ;
                #pragma unroll
                for (int j = 0; j < 7; ++j) {
                    const int cgl = wn * 56 + j * 8 + 2 * tg;   // even, 0..110
                    if (cgl < OUT_SZ) {
                        *(float2*)(orow + cgl) =
                            make_float2(acc[t][j][0], acc[t][j][1]);
                        *(float2*)(orow + (size_t)8 * OUT_LD + cgl) =
                            make_float2(acc[t][j][2], acc[t][j][3]);
                    }
                    #pragma unroll
                    for (int q = 0; q < 4; ++q) acc[t][j][q] = 0.0f;
                }
            }
        }
    }
}

// ---------------------------------------------------------------------------
extern "C" void kernel_launch(void* const* d_in, const int* in_sizes, int n_in,
                              void* d_out, int out_size) {
    const float* x = (const float*)d_in[0];   // [32768, 4000]
    const float* W = (const float*)d_in[1];   // [2000, 4000]
    float* out = (float*)d_out;               // [32768, 2000]

    static bool attr_set = false;
    if (!attr_set) {
        cudaFuncSetAttribute(ensemble_linear_f16m_kernel,
                             cudaFuncAttributeMaxDynamicSharedMemorySize,
                             SMEM_BYTES);
        attr_set = true;
    }

    ensemble_linear_f16m_kernel<<<NCTAS, THREADS, SMEM_BYTES>>>(x, W, out);
}